// round 1
// baseline (speedup 1.0000x reference)
#include <cuda_runtime.h>
#include <math.h>

#define EMBX 300
#define HX 512
#define HHX 256
#define BX 128
#define LX 128
#define NX (BX*LX)          /* 16384 */
#define SX 10
#define LAYERSX 7

#define SZ_HID (NX*2*HX)            /* 16777216 */
#define OFF_GE SZ_HID
#define SZ_GE (2*BX*HX)             /* 131072  */
#define OFF_OV (SZ_HID + SZ_GE)     /* 16908288 */

// ---------------- scratch (device globals; no allocation allowed) ----------
__device__ __align__(16) float g_emb[(size_t)NX*EMBX];
__device__ __align__(16) float g_xp[2][(size_t)NX*4*HHX];
__device__ __align__(16) float g_nrep[(size_t)(NX+1)*HX];
__device__ __align__(16) float g_hid[2][2][(size_t)(NX+1)*HX];
__device__ __align__(16) float g_cat[(size_t)NX*2*HX];
__device__ __align__(16) float g_len[2][NX];
__device__ __align__(16) float g_bias[2][4*HHX];
__device__ __align__(16) float g_whhq[2][HHX*HHX*4];

// ---------------- embedding lookup ----------------
__global__ void k_embed(const int* __restrict__ feat, const float* __restrict__ Wemb)
{
    int idx = blockIdx.x * blockDim.x + threadIdx.x;
    if (idx >= NX*EMBX) return;
    int n = idx / EMBX, e = idx - n*EMBX;
    g_emb[idx] = Wemb[(size_t)feat[n]*EMBX + e];
}

// ---------------- bias precompute bih+bhh ----------------
__global__ void k_bias(const float* bihf, const float* bhhf,
                       const float* bihb, const float* bhhb)
{
    int j = blockIdx.x * blockDim.x + threadIdx.x;
    if (j < 4*HHX) {
        g_bias[0][j] = bihf[j] + bhhf[j];
        g_bias[1][j] = bihb[j] + bhhb[j];
    }
}

// ---------------- Whh transpose into [k][j][{i,f,g,o}] float4 layout --------
__global__ void k_whhq(const float* __restrict__ Wf, const float* __restrict__ Wb)
{
    int idx = blockIdx.x * blockDim.x + threadIdx.x;
    if (idx >= 2*HHX*HHX) return;
    int d = idx / (HHX*HHX);
    int rem = idx - d*(HHX*HHX);
    int k = rem / HHX, j = rem - k*HHX;
    const float* W = d ? Wb : Wf;
    float4 v;
    v.x = W[(size_t)(0*HHX + j)*HHX + k];
    v.y = W[(size_t)(1*HHX + j)*HHX + k];
    v.z = W[(size_t)(2*HHX + j)*HHX + k];
    v.w = W[(size_t)(3*HHX + j)*HHX + k];
    *(float4*)&g_whhq[d][(size_t)rem*4] = v;
}

// ---------------- generic fp32 GEMM: C = A(MxK) * Wt(NxK)^T + bias, opt relu
__global__ __launch_bounds__(256) void k_gemm(
    const float* __restrict__ A, const float* __restrict__ Wt,
    const float* __restrict__ bias, float* __restrict__ C,
    int M, int N, int K, int relu)
{
    __shared__ float As[16][128];
    __shared__ float Ws[16][128];
    const int tid = threadIdx.x;
    const int tx = tid & 15, ty = tid >> 4;
    const int row0 = blockIdx.y * 128, col0 = blockIdx.x * 128;
    float acc[8][8];
#pragma unroll
    for (int i = 0; i < 8; i++)
#pragma unroll
        for (int j = 0; j < 8; j++) acc[i][j] = 0.f;

    for (int k0 = 0; k0 < K; k0 += 16) {
#pragma unroll
        for (int i = 0; i < 8; i++) {
            int e = tid + i*256;
            int kk = e & 15, r = e >> 4;
            int gk = k0 + kk;
            As[kk][r] = (gk < K) ? A[(size_t)(row0 + r)*K + gk] : 0.f;
            Ws[kk][r] = (gk < K) ? Wt[(size_t)(col0 + r)*K + gk] : 0.f;
        }
        __syncthreads();
#pragma unroll
        for (int kk = 0; kk < 16; kk++) {
            float4 a0 = *(const float4*)&As[kk][ty*4];
            float4 a1 = *(const float4*)&As[kk][64 + ty*4];
            float4 w0 = *(const float4*)&Ws[kk][tx*4];
            float4 w1 = *(const float4*)&Ws[kk][64 + tx*4];
            float af[8] = {a0.x,a0.y,a0.z,a0.w,a1.x,a1.y,a1.z,a1.w};
            float wf[8] = {w0.x,w0.y,w0.z,w0.w,w1.x,w1.y,w1.z,w1.w};
#pragma unroll
            for (int i = 0; i < 8; i++)
#pragma unroll
                for (int j = 0; j < 8; j++)
                    acc[i][j] = fmaf(af[i], wf[j], acc[i][j]);
        }
        __syncthreads();
    }
#pragma unroll
    for (int i = 0; i < 8; i++) {
        int gr = row0 + ((i < 4) ? (ty*4 + i) : (64 + ty*4 + i - 4));
        int gc0 = col0 + tx*4;
        float4 v0, v1;
        v0.x = acc[i][0] + bias[gc0+0];
        v0.y = acc[i][1] + bias[gc0+1];
        v0.z = acc[i][2] + bias[gc0+2];
        v0.w = acc[i][3] + bias[gc0+3];
        v1.x = acc[i][4] + bias[gc0+64+0];
        v1.y = acc[i][5] + bias[gc0+64+1];
        v1.z = acc[i][6] + bias[gc0+64+2];
        v1.w = acc[i][7] + bias[gc0+64+3];
        if (relu) {
            v0.x = fmaxf(v0.x, 0.f); v0.y = fmaxf(v0.y, 0.f);
            v0.z = fmaxf(v0.z, 0.f); v0.w = fmaxf(v0.w, 0.f);
            v1.x = fmaxf(v1.x, 0.f); v1.y = fmaxf(v1.y, 0.f);
            v1.z = fmaxf(v1.z, 0.f); v1.w = fmaxf(v1.w, 0.f);
        }
        *(float4*)&C[(size_t)gr*N + gc0]      = v0;
        *(float4*)&C[(size_t)gr*N + gc0 + 64] = v1;
    }
}

// ---------------- persistent BiLSTM: 64 blocks = 2 dirs x 16 rowgroups(4) ---
__global__ __launch_bounds__(256) void k_lstm()
{
    const int dir = blockIdx.x >> 5;
    const int rg  = blockIdx.x & 31;
    const int j = threadIdx.x;  // hidden index 0..255
    const float* __restrict__ Wq = g_whhq[dir];
    const float* __restrict__ xp = g_xp[dir];
    __shared__ float hbuf[2][4][HHX];
#pragma unroll
    for (int r = 0; r < 4; r++) hbuf[0][r][j] = 0.f;
    float c[4] = {0.f, 0.f, 0.f, 0.f};
    __syncthreads();
    int p = 0;
    for (int t = 0; t < LX; t++) {
        const int tseq = dir ? (LX - 1 - t) : t;
        float a0[4] = {0,0,0,0}, a1[4] = {0,0,0,0};
        float a2[4] = {0,0,0,0}, a3[4] = {0,0,0,0};
#pragma unroll 4
        for (int k = 0; k < HHX; k++) {
            float4 w = *(const float4*)&Wq[((size_t)k*HHX + j)*4];
#pragma unroll
            for (int r = 0; r < 4; r++) {
                float hv = hbuf[p][r][k];
                a0[r] = fmaf(w.x, hv, a0[r]);
                a1[r] = fmaf(w.y, hv, a1[r]);
                a2[r] = fmaf(w.z, hv, a2[r]);
                a3[r] = fmaf(w.w, hv, a3[r]);
            }
        }
#pragma unroll
        for (int r = 0; r < 4; r++) {
            const int row = rg*4 + r;
            const size_t nidx = (size_t)row*LX + tseq;
            const float* xr = xp + nidx*(4*HHX);
            float gi = a0[r] + xr[j];
            float gf = a1[r] + xr[HHX + j];
            float gg = a2[r] + xr[2*HHX + j];
            float go = a3[r] + xr[3*HHX + j];
            float si = 1.f/(1.f + expf(-gi));
            float sf = 1.f/(1.f + expf(-gf));
            float so = 1.f/(1.f + expf(-go));
            float tg = tanhf(gg);
            c[r] = sf*c[r] + si*tg;
            float hv = so * tanhf(c[r]);
            hbuf[p ^ 1][r][j] = hv;
            g_nrep[nidx*HX + (size_t)dir*HHX + j] = hv;
        }
        __syncthreads();
        p ^= 1;
    }
}

// ---------------- padding row + zero row N of hidden buffers ----------------
__global__ void k_pad_zero(const float* __restrict__ pad)
{
    int j = threadIdx.x;
    if (j < HX) {
        g_nrep[(size_t)NX*HX + j] = pad[j];
        g_hid[0][0][(size_t)NX*HX + j] = 0.f;
        g_hid[0][1][(size_t)NX*HX + j] = 0.f;
        g_hid[1][0][(size_t)NX*HX + j] = 0.f;
        g_hid[1][1][(size_t)NX*HX + j] = 0.f;
    }
}

// ---------------- initial hidden = node_repres[batch_nodes] ----------------
__global__ void k_init_hid(const int* __restrict__ nodes)
{
    int idx = blockIdx.x * blockDim.x + threadIdx.x;
    if (idx >= NX*HX) return;
    int n = idx >> 9, cc = idx & (HX - 1);
    float v = g_nrep[(size_t)nodes[n]*HX + cc];
    g_hid[0][0][idx] = v;
    g_hid[1][0][idx] = v;
}

// ---------------- neighbor-count (layer 0 only) ----------------
__global__ void k_len(const int* __restrict__ nodes,
                      const int* __restrict__ adjF, const int* __restrict__ adjB)
{
    const int n = blockIdx.x;
    const int d = blockIdx.y;
    const int* adj = d ? adjB : adjF;
    const int node = nodes[n];
    const int lane = threadIdx.x & 31, w = threadIdx.x >> 5;
    __shared__ float cnt;
    if (threadIdx.x == 0) cnt = 0.f;
    __syncthreads();
    float local = 0.f;
    for (int s = w; s < SX; s += 4) {
        int nb = adj[(size_t)node*SX + s];
        const float* rowp = g_nrep + (size_t)nb*HX;
        float sum = 0.f;
        for (int ccc = lane; ccc < HX; ccc += 32) {
            float v = rowp[ccc];
            sum += (v > 0.f) ? v : 0.f;
        }
#pragma unroll
        for (int o = 16; o; o >>= 1) sum += __shfl_xor_sync(0xffffffffu, sum, o);
        if (lane == 0 && sum > 0.f) local += 1.f;
    }
    if (lane == 0) atomicAdd(&cnt, local);
    __syncthreads();
    if (threadIdx.x == 0) g_len[d][n] = cnt;
}

// ------- gather + mean + concat:  cat = [self | mean(neigh)] ---------------
__global__ __launch_bounds__(128) void k_gm(
    const float* __restrict__ selfT, const float* __restrict__ neighT,
    const int* __restrict__ nodes, const int* __restrict__ adj,
    const float* __restrict__ len)
{
    const int n = blockIdx.x;
    const int t = threadIdx.x;
    __shared__ int nb[SX];
    __shared__ float invlen;
    if (t < SX) nb[t] = adj[(size_t)nodes[n]*SX + t];
    if (t == 0) invlen = 1.f / len[n];
    __syncthreads();
    const int c = t * 4;
    float4 s = {0.f, 0.f, 0.f, 0.f};
#pragma unroll
    for (int q = 0; q < SX; q++) {
        const float4 v = *(const float4*)&neighT[(size_t)nb[q]*HX + c];
        s.x += v.x; s.y += v.y; s.z += v.z; s.w += v.w;
    }
    float4 sv = *(const float4*)&selfT[(size_t)n*HX + c];
    *(float4*)&g_cat[(size_t)n*2*HX + c] = sv;
    float4 m = {s.x*invlen, s.y*invlen, s.z*invlen, s.w*invlen};
    *(float4*)&g_cat[(size_t)n*2*HX + HX + c] = m;
}

// ---------------- finalize: hidden concat + output_vector ------------------
__global__ void k_finalize(float* __restrict__ out, int fin)
{
    int idx = blockIdx.x * blockDim.x + threadIdx.x;
    if (idx >= NX*HX) return;
    int n = idx >> 9, cc = idx & (HX - 1);
    out[(size_t)n*1024 + cc]       = g_hid[0][fin][idx];
    out[(size_t)n*1024 + 512 + cc] = g_hid[1][fin][idx];
    out[(size_t)OFF_OV + idx]      = g_nrep[idx];
}

// ---------------- max pool over L -> graph_embedding -----------------------
__global__ void k_pool(const float* __restrict__ hid, float* __restrict__ ge)
{
    const int b = blockIdx.x;
    const int jx = threadIdx.x; // 0..1023
    float m = -3.402823466e38f;
    const float* base = hid + (size_t)b*LX*1024 + jx;
    for (int l = 0; l < LX; l++) m = fmaxf(m, base[(size_t)l*1024]);
    ge[(size_t)b*1024 + jx] = m;
}

// ============================ host launcher ================================
extern "C" void kernel_launch(void* const* d_in, const int* in_sizes, int n_in,
                              void* d_out, int out_size)
{
    const int*   feature_info = (const int*)d_in[0];
    const int*   batch_nodes  = (const int*)d_in[1];
    const int*   fw_adj       = (const int*)d_in[2];
    const int*   bw_adj       = (const int*)d_in[3];
    const float* W_emb        = (const float*)d_in[4];
    const float* Wih_f        = (const float*)d_in[5];
    const float* Whh_f        = (const float*)d_in[6];
    const float* bih_f        = (const float*)d_in[7];
    const float* bhh_f        = (const float*)d_in[8];
    const float* Wih_b        = (const float*)d_in[9];
    const float* Whh_b        = (const float*)d_in[10];
    const float* bih_b        = (const float*)d_in[11];
    const float* bhh_b        = (const float*)d_in[12];
    const float* padding_vec  = (const float*)d_in[13];
    const float* fw_W         = (const float*)d_in[14];
    const float* fw_b         = (const float*)d_in[15];
    const float* bw_W         = (const float*)d_in[16];
    const float* bw_b         = (const float*)d_in[17];
    float* out = (float*)d_out;

    float *p_emb, *p_xp, *p_nrep, *p_hid, *p_cat, *p_len, *p_bias;
    cudaGetSymbolAddress((void**)&p_emb,  g_emb);
    cudaGetSymbolAddress((void**)&p_xp,   g_xp);
    cudaGetSymbolAddress((void**)&p_nrep, g_nrep);
    cudaGetSymbolAddress((void**)&p_hid,  g_hid);
    cudaGetSymbolAddress((void**)&p_cat,  g_cat);
    cudaGetSymbolAddress((void**)&p_len,  g_len);
    cudaGetSymbolAddress((void**)&p_bias, g_bias);

    float* xp_d[2]  = { p_xp, p_xp + (size_t)NX*4*HHX };
    float* hid_d[2][2];
    for (int d = 0; d < 2; d++)
        for (int q = 0; q < 2; q++)
            hid_d[d][q] = p_hid + ((size_t)d*2 + q) * ((size_t)(NX+1)*HX);

    // 1. embedding
    k_embed<<<(NX*EMBX + 255)/256, 256>>>(feature_info, W_emb);
    // 2. bias sums + Whh transpose
    k_bias<<<4, 256>>>(bih_f, bhh_f, bih_b, bhh_b);
    k_whhq<<<(2*HHX*HHX + 255)/256, 256>>>(Whh_f, Whh_b);
    // 3. input projections xp = emb @ Wih^T + (bih+bhh)
    dim3 gxp(4*HHX/128, NX/128);
    k_gemm<<<gxp, 256>>>(p_emb, Wih_f, p_bias,          xp_d[0], NX, 4*HHX, EMBX, 0);
    k_gemm<<<gxp, 256>>>(p_emb, Wih_b, p_bias + 4*HHX,  xp_d[1], NX, 4*HHX, EMBX, 0);
    // 4. persistent BiLSTM -> g_nrep rows 0..N-1
    k_lstm<<<64, 256>>>();
    // 5. padding row + zero rows
    k_pad_zero<<<1, 512>>>(padding_vec);
    // 6. initial hidden
    k_init_hid<<<(NX*HX + 255)/256, 256>>>(batch_nodes);
    // 7. neighbor lengths (layer-0 semantics, reused for all layers)
    k_len<<<dim3(NX, 2), 128>>>(batch_nodes, fw_adj, bw_adj);

    // 8. 7 SAGE layers x 2 directions
    int pin = 0;
    dim3 gsage(HX/128, NX/128);
    for (int l = 0; l < LAYERSX; l++) {
        for (int d = 0; d < 2; d++) {
            const float* neighT = (l == 0) ? p_nrep : hid_d[d][pin];
            const int*   adj    = d ? bw_adj : fw_adj;
            k_gm<<<NX, 128>>>(hid_d[d][pin], neighT, batch_nodes, adj,
                              p_len + (size_t)d*NX);
            const float* W  = (d ? bw_W : fw_W) + (size_t)l*HX*2*HX;
            const float* bb = (d ? bw_b : fw_b) + (size_t)l*HX;
            k_gemm<<<gsage, 256>>>(p_cat, W, bb, hid_d[d][1 - pin],
                                   NX, HX, 2*HX, 1);
        }
        pin ^= 1;
    }
    // after 7 layers final hidden sits in buffer index `pin` (= 1)
    // 9. outputs
    k_finalize<<<(NX*HX + 255)/256, 256>>>(out, pin);
    k_pool<<<BX, 1024>>>(out, out + OFF_GE);
    (void)in_sizes; (void)n_in; (void)out_size;
}

// round 6
// speedup vs baseline: 2.2619x; 2.2619x over previous
#include <cuda_runtime.h>
#include <cuda_bf16.h>
#include <math.h>
#include <stdint.h>

#define EMBX 300
#define EMBP 320
#define HX 512
#define HHX 256
#define BX 128
#define LX 128
#define NX (BX*LX)          /* 16384 */
#define SX 10
#define LAYERSX 7
#define K_SAGE 1024

#define SZ_HID (NX*2*HX)
#define OFF_GE SZ_HID
#define OFF_OV (SZ_HID + 2*BX*HX)

// ---------------- scratch (device globals) ----------------
__device__ __align__(16) __nv_bfloat16 g_embh[(size_t)NX*EMBP];
__device__ __align__(16) __nv_bfloat16 g_embl[(size_t)NX*EMBP];
__device__ __align__(16) __nv_bfloat16 g_wihh[2][(size_t)1024*EMBP];
__device__ __align__(16) __nv_bfloat16 g_wihl[2][(size_t)1024*EMBP];
__device__ __align__(16) __nv_bfloat16 g_wh[2][LAYERSX][(size_t)HX*K_SAGE];
__device__ __align__(16) __nv_bfloat16 g_wl[2][LAYERSX][(size_t)HX*K_SAGE];
__device__ __align__(16) __nv_bfloat16 g_cath[(size_t)NX*K_SAGE];
__device__ __align__(16) __nv_bfloat16 g_catl[(size_t)NX*K_SAGE];
__device__ __align__(16) float g_xp[2][(size_t)NX*1024];
__device__ __align__(16) float g_nrep[(size_t)(NX+1)*HX];
__device__ __align__(16) float g_hid[2][2][(size_t)(NX+1)*HX];
__device__ __align__(16) float g_len[2][NX];
__device__ __align__(16) float g_bias[2][1024];
__device__ __align__(16) float g_whhq[2][HHX*HHX*4];

// ---------------- helpers ----------------
#define SWZ(o) ((o) ^ (((o) >> 3) & 0x70))

__device__ __forceinline__ uint32_t s2u(const void* p) {
    uint32_t a;
    asm("{ .reg .u64 t; cvta.to.shared.u64 t, %1; cvt.u32.u64 %0, t; }"
        : "=r"(a) : "l"(p));
    return a;
}
__device__ __forceinline__ void cpa16(uint32_t d, const void* g) {
    asm volatile("cp.async.cg.shared.global [%0], [%1], 16;" :: "r"(d), "l"(g));
}
__device__ __forceinline__ void ldsm4(uint32_t* r, uint32_t addr) {
    asm volatile("ldmatrix.sync.aligned.m8n8.x4.shared.b16 {%0,%1,%2,%3}, [%4];"
        : "=r"(r[0]), "=r"(r[1]), "=r"(r[2]), "=r"(r[3]) : "r"(addr));
}
__device__ __forceinline__ void mma16816(float* d, const uint32_t* a, const uint32_t* b) {
    asm volatile("mma.sync.aligned.m16n8k16.row.col.f32.bf16.bf16.f32 "
        "{%0,%1,%2,%3}, {%4,%5,%6,%7}, {%8,%9}, {%0,%1,%2,%3};"
        : "+f"(d[0]), "+f"(d[1]), "+f"(d[2]), "+f"(d[3])
        : "r"(a[0]), "r"(a[1]), "r"(a[2]), "r"(a[3]), "r"(b[0]), "r"(b[1]));
}
__device__ __forceinline__ void bsplit(float a, __nv_bfloat16& h, __nv_bfloat16& l) {
    h = __float2bfloat16(a);
    l = __float2bfloat16(a - __bfloat162float(h));
}

// ---------------- embedding lookup -> bf16 hi/lo, K padded to 320 ----------
__global__ void k_embed(const int* __restrict__ feat, const float* __restrict__ Wemb)
{
    int idx = blockIdx.x * blockDim.x + threadIdx.x;
    if (idx >= NX*EMBP) return;
    int n = idx / EMBP, e = idx - n*EMBP;
    float v = 0.f;
    if (e < EMBX) v = Wemb[(size_t)feat[n]*EMBX + e];
    __nv_bfloat16 h, l; bsplit(v, h, l);
    g_embh[idx] = h; g_embl[idx] = l;
}

// ---------------- bias precompute bih+bhh ----------------
__global__ void k_bias(const float* bihf, const float* bhhf,
                       const float* bihb, const float* bhhb)
{
    int j = blockIdx.x * blockDim.x + threadIdx.x;
    if (j < 4*HHX) {
        g_bias[0][j] = bihf[j] + bhhf[j];
        g_bias[1][j] = bihb[j] + bhhb[j];
    }
}

// ---------------- Wih split -> bf16 hi/lo, padded to 320 -------------------
__global__ void k_split_wih(const float* __restrict__ Wf, const float* __restrict__ Wb)
{
    int idx = blockIdx.x * blockDim.x + threadIdx.x;
    if (idx >= 2*1024*EMBP) return;
    int d = idx / (1024*EMBP);
    int rem = idx - d*(1024*EMBP);
    int r = rem / EMBP, e = rem - r*EMBP;
    const float* W = d ? Wb : Wf;
    float v = (e < EMBX) ? W[(size_t)r*EMBX + e] : 0.f;
    __nv_bfloat16 h, l; bsplit(v, h, l);
    g_wihh[d][rem] = h; g_wihl[d][rem] = l;
}

// ---------------- SAGE W split -> bf16 hi/lo -------------------------------
__global__ void k_split_sagew(const float* __restrict__ Wf, const float* __restrict__ Wb)
{
    const int per = LAYERSX*HX*K_SAGE;
    int idx = blockIdx.x * blockDim.x + threadIdx.x;
    if (idx >= 2*per) return;
    int d = idx / per, rem = idx - d*per;
    float v = (d ? Wb : Wf)[rem];
    __nv_bfloat16 h, l; bsplit(v, h, l);
    (&g_wh[0][0][0])[(size_t)d*per + rem] = h;
    (&g_wl[0][0][0])[(size_t)d*per + rem] = l;
}

// ---------------- Whh transpose into [k][j][{i,f,g,o}] float4 layout --------
__global__ void k_whhq(const float* __restrict__ Wf, const float* __restrict__ Wb)
{
    int idx = blockIdx.x * blockDim.x + threadIdx.x;
    if (idx >= 2*HHX*HHX) return;
    int d = idx / (HHX*HHX);
    int rem = idx - d*(HHX*HHX);
    int k = rem / HHX, j = rem - k*HHX;
    const float* W = d ? Wb : Wf;
    float4 v;
    v.x = W[(size_t)(0*HHX + j)*HHX + k];
    v.y = W[(size_t)(1*HHX + j)*HHX + k];
    v.z = W[(size_t)(2*HHX + j)*HHX + k];
    v.w = W[(size_t)(3*HHX + j)*HHX + k];
    *(float4*)&g_whhq[d][(size_t)rem*4] = v;
}

// ============ mma.sync bf16x3 GEMM: C = split(A) @ split(B)^T + bias ========
// A: M x K bf16 hi/lo (K-major), B: Ncols x K bf16 hi/lo (K-major), C fp32.
// Tile 128x128, BK=64 (128B rows, SW128 swizzle), 2-stage cp.async pipeline.
// Stage layout: Ah @0, Al @16K, Bh @32K, Bl @48K (each 128 rows x 128B).
__device__ __forceinline__ void load_stage(
    uint32_t sb, int s, int kc,
    const char* A0, const char* A1, const char* B0, const char* B1,
    int K, int tid)
{
    const char* srcs[4] = { A0, A1, B0, B1 };
    uint32_t stb = sb + s*65536;
#pragma unroll
    for (int t4 = 0; t4 < 4; t4++) {
        const char* src = srcs[t4] + (size_t)kc*128;
        uint32_t tb = stb + t4*16384;
#pragma unroll
        for (int i = 0; i < 4; i++) {
            int q = tid + i*256;
            int r = q >> 3, sc = q & 7;
            cpa16(tb + SWZ(r*128 + sc*16), src + (size_t)r*(size_t)K*2 + sc*16);
        }
    }
    asm volatile("cp.async.commit_group;" ::: "memory");
}

__global__ __launch_bounds__(256, 1) void k_mma_gemm(
    const __nv_bfloat16* __restrict__ Ah, const __nv_bfloat16* __restrict__ Al,
    const __nv_bfloat16* __restrict__ Bh, const __nv_bfloat16* __restrict__ Bl,
    const float* __restrict__ bias, float* __restrict__ C,
    int Ncols, int K, int relu)
{
    extern __shared__ char dsm[];
    const int tid = threadIdx.x;
    const int wid = tid >> 5, lane = tid & 31;
    const int row0 = blockIdx.y << 7;
    const int col0 = blockIdx.x << 7;
    const int nch = K >> 6;

    uint32_t sb = s2u(dsm);
    sb = (sb + 1023u) & ~1023u;

    const char* A0 = (const char*)(Ah + (size_t)row0*K);
    const char* A1 = (const char*)(Al + (size_t)row0*K);
    const char* B0 = (const char*)(Bh + (size_t)col0*K);
    const char* B1 = (const char*)(Bl + (size_t)col0*K);

    // warp tile: 32 rows x 64 cols; 8 warps = 4x2
    const int wm = (wid >> 1) * 32;
    const int wn = (wid & 1) * 64;

    // ldmatrix lane -> (row, 16B-col) within tile
    const int gq8 = lane >> 3, lr = lane & 7;
    const int a_row = wm + lr + ((gq8 & 1) << 3);
    const int a_cb  = (gq8 >> 1) << 4;
    const int b_row = wn + lr + ((gq8 >> 1) << 3);
    const int b_cb  = (gq8 & 1) << 4;

    float acc[2][8][4];
#pragma unroll
    for (int mt = 0; mt < 2; mt++)
#pragma unroll
        for (int nt = 0; nt < 8; nt++)
#pragma unroll
            for (int j = 0; j < 4; j++) acc[mt][nt][j] = 0.f;

    load_stage(sb, 0, 0, A0, A1, B0, B1, K, tid);
    load_stage(sb, 1, 1, A0, A1, B0, B1, K, tid);

    for (int kc = 0; kc < nch; kc++) {
        const int s = kc & 1;
        if (kc + 1 < nch)
            asm volatile("cp.async.wait_group 1;" ::: "memory");
        else
            asm volatile("cp.async.wait_group 0;" ::: "memory");
        __syncthreads();
        const uint32_t stb = sb + s*65536;
#pragma unroll
        for (int ks = 0; ks < 4; ks++) {
            const int k0b = ks * 32;
            uint32_t ah[2][4], al[2][4];
#pragma unroll
            for (int mt = 0; mt < 2; mt++) {
                uint32_t off = SWZ((uint32_t)((a_row + mt*16)*128 + (a_cb + k0b)));
                ldsm4(ah[mt], stb + off);
                ldsm4(al[mt], stb + 16384 + off);
            }
            uint32_t bh[4][4], bl[4][4];
#pragma unroll
            for (int gg = 0; gg < 4; gg++) {
                uint32_t off = SWZ((uint32_t)((b_row + gg*16)*128 + (b_cb + k0b)));
                ldsm4(bh[gg], stb + 32768 + off);
                ldsm4(bl[gg], stb + 49152 + off);
            }
#pragma unroll
            for (int mt = 0; mt < 2; mt++)
#pragma unroll
                for (int nt = 0; nt < 8; nt++) {
                    const uint32_t* bhp = &bh[nt >> 1][(nt & 1) * 2];
                    const uint32_t* blp = &bl[nt >> 1][(nt & 1) * 2];
                    mma16816(acc[mt][nt], ah[mt], bhp);
                    mma16816(acc[mt][nt], ah[mt], blp);
                    mma16816(acc[mt][nt], al[mt], bhp);
                }
        }
        __syncthreads();
        if (kc + 2 < nch)
            load_stage(sb, s, kc + 2, A0, A1, B0, B1, K, tid);
    }

    // epilogue: acc -> C with bias (+relu)
    const int erow = row0 + wm + (lane >> 2);
    const int ecol = col0 + wn + 2*(lane & 3);
#pragma unroll
    for (int mt = 0; mt < 2; mt++)
#pragma unroll
        for (int nt = 0; nt < 8; nt++) {
            int r = erow + mt*16;
            int cc = ecol + nt*8;
            float2 v0, v1;
            v0.x = acc[mt][nt][0] + bias[cc];
            v0.y = acc[mt][nt][1] + bias[cc+1];
            v1.x = acc[mt][nt][2] + bias[cc];
            v1.y = acc[mt][nt][3] + bias[cc+1];
            if (relu) {
                v0.x = fmaxf(v0.x, 0.f); v0.y = fmaxf(v0.y, 0.f);
                v1.x = fmaxf(v1.x, 0.f); v1.y = fmaxf(v1.y, 0.f);
            }
            *(float2*)&C[(size_t)r*Ncols + cc]     = v0;
            *(float2*)&C[(size_t)(r+8)*Ncols + cc] = v1;
        }
}

// ---------------- persistent BiLSTM ----------------
__global__ __launch_bounds__(256) void k_lstm()
{
    const int dir = blockIdx.x >> 5;
    const int rg  = blockIdx.x & 31;
    const int j = threadIdx.x;
    const float* __restrict__ Wq = g_whhq[dir];
    const float* __restrict__ xp = g_xp[dir];
    __shared__ float hbuf[2][4][HHX];
#pragma unroll
    for (int r = 0; r < 4; r++) hbuf[0][r][j] = 0.f;
    float c[4] = {0.f, 0.f, 0.f, 0.f};
    __syncthreads();
    int p = 0;
    for (int t = 0; t < LX; t++) {
        const int tseq = dir ? (LX - 1 - t) : t;
        float a0[4] = {0,0,0,0}, a1[4] = {0,0,0,0};
        float a2[4] = {0,0,0,0}, a3[4] = {0,0,0,0};
#pragma unroll 4
        for (int k = 0; k < HHX; k++) {
            float4 w = *(const float4*)&Wq[((size_t)k*HHX + j)*4];
#pragma unroll
            for (int r = 0; r < 4; r++) {
                float hv = hbuf[p][r][k];
                a0[r] = fmaf(w.x, hv, a0[r]);
                a1[r] = fmaf(w.y, hv, a1[r]);
                a2[r] = fmaf(w.z, hv, a2[r]);
                a3[r] = fmaf(w.w, hv, a3[r]);
            }
        }
#pragma unroll
        for (int r = 0; r < 4; r++) {
            const int row = rg*4 + r;
            const size_t nidx = (size_t)row*LX + tseq;
            const float* xr = xp + nidx*(4*HHX);
            float gi = a0[r] + xr[j];
            float gf = a1[r] + xr[HHX + j];
            float gg = a2[r] + xr[2*HHX + j];
            float go = a3[r] + xr[3*HHX + j];
            float si = 1.f/(1.f + expf(-gi));
            float sf = 1.f/(1.f + expf(-gf));
            float so = 1.f/(1.f + expf(-go));
            float tg = tanhf(gg);
            c[r] = sf*c[r] + si*tg;
            float hv = so * tanhf(c[r]);
            hbuf[p ^ 1][r][j] = hv;
            g_nrep[nidx*HX + (size_t)dir*HHX + j] = hv;
        }
        __syncthreads();
        p ^= 1;
    }
}

// ---------------- padding row + zero row N of hidden buffers ----------------
__global__ void k_pad_zero(const float* __restrict__ pad)
{
    int j = threadIdx.x;
    if (j < HX) {
        g_nrep[(size_t)NX*HX + j] = pad[j];
        g_hid[0][0][(size_t)NX*HX + j] = 0.f;
        g_hid[0][1][(size_t)NX*HX + j] = 0.f;
        g_hid[1][0][(size_t)NX*HX + j] = 0.f;
        g_hid[1][1][(size_t)NX*HX + j] = 0.f;
    }
}

// ---------------- initial hidden = node_repres[batch_nodes] ----------------
__global__ void k_init_hid(const int* __restrict__ nodes)
{
    int idx = blockIdx.x * blockDim.x + threadIdx.x;
    if (idx >= NX*HX) return;
    int n = idx >> 9, cc = idx & (HX - 1);
    float v = g_nrep[(size_t)nodes[n]*HX + cc];
    g_hid[0][0][idx] = v;
    g_hid[1][0][idx] = v;
}

// ---------------- neighbor-count (layer 0 only) ----------------
__global__ void k_len(const int* __restrict__ nodes,
                      const int* __restrict__ adjF, const int* __restrict__ adjB)
{
    const int n = blockIdx.x;
    const int d = blockIdx.y;
    const int* adj = d ? adjB : adjF;
    const int node = nodes[n];
    const int lane = threadIdx.x & 31, w = threadIdx.x >> 5;
    __shared__ float cnt;
    if (threadIdx.x == 0) cnt = 0.f;
    __syncthreads();
    float local = 0.f;
    for (int s = w; s < SX; s += 4) {
        int nb = adj[(size_t)node*SX + s];
        const float* rowp = g_nrep + (size_t)nb*HX;
        float sum = 0.f;
        for (int ccc = lane; ccc < HX; ccc += 32) {
            float v = rowp[ccc];
            sum += (v > 0.f) ? v : 0.f;
        }
#pragma unroll
        for (int o = 16; o; o >>= 1) sum += __shfl_xor_sync(0xffffffffu, sum, o);
        if (lane == 0 && sum > 0.f) local += 1.f;
    }
    if (lane == 0) atomicAdd(&cnt, local);
    __syncthreads();
    if (threadIdx.x == 0) g_len[d][n] = cnt;
}

// ------- gather + mean + concat -> bf16 hi/lo cat matrix -------------------
__global__ __launch_bounds__(128) void k_gm(
    const float* __restrict__ selfT, const float* __restrict__ neighT,
    const int* __restrict__ nodes, const int* __restrict__ adj,
    const float* __restrict__ len)
{
    const int n = blockIdx.x;
    const int t = threadIdx.x;
    __shared__ int nb[SX];
    __shared__ float invlen;
    if (t < SX) nb[t] = adj[(size_t)nodes[n]*SX + t];
    if (t == 0) invlen = 1.f / len[n];
    __syncthreads();
    const int c = t * 4;
    float4 s = {0.f, 0.f, 0.f, 0.f};
#pragma unroll
    for (int q = 0; q < SX; q++) {
        const float4 v = *(const float4*)&neighT[(size_t)nb[q]*HX + c];
        s.x += v.x; s.y += v.y; s.z += v.z; s.w += v.w;
    }
    float4 sv = *(const float4*)&selfT[(size_t)n*HX + c];
    float4 m = {s.x*invlen, s.y*invlen, s.z*invlen, s.w*invlen};

    size_t o = (size_t)n*K_SAGE + c;
    __nv_bfloat16 h0,l0,h1,l1,h2,l2,h3,l3;
    bsplit(sv.x,h0,l0); bsplit(sv.y,h1,l1); bsplit(sv.z,h2,l2); bsplit(sv.w,h3,l3);
    *(__nv_bfloat162*)&g_cath[o]   = __halves2bfloat162(h0,h1);
    *(__nv_bfloat162*)&g_cath[o+2] = __halves2bfloat162(h2,h3);
    *(__nv_bfloat162*)&g_catl[o]   = __halves2bfloat162(l0,l1);
    *(__nv_bfloat162*)&g_catl[o+2] = __halves2bfloat162(l2,l3);

    bsplit(m.x,h0,l0); bsplit(m.y,h1,l1); bsplit(m.z,h2,l2); bsplit(m.w,h3,l3);
    *(__nv_bfloat162*)&g_cath[o+HX]   = __halves2bfloat162(h0,h1);
    *(__nv_bfloat162*)&g_cath[o+HX+2] = __halves2bfloat162(h2,h3);
    *(__nv_bfloat162*)&g_catl[o+HX]   = __halves2bfloat162(l0,l1);
    *(__nv_bfloat162*)&g_catl[o+HX+2] = __halves2bfloat162(l2,l3);
}

// ---------------- finalize + pool ----------------
__global__ void k_finalize(float* __restrict__ out, int fin)
{
    int idx = blockIdx.x * blockDim.x + threadIdx.x;
    if (idx >= NX*HX) return;
    int n = idx >> 9, cc = idx & (HX - 1);
    out[(size_t)n*1024 + cc]       = g_hid[0][fin][idx];
    out[(size_t)n*1024 + 512 + cc] = g_hid[1][fin][idx];
    out[(size_t)OFF_OV + idx]      = g_nrep[idx];
}

__global__ void k_pool(const float* __restrict__ hid, float* __restrict__ ge)
{
    const int b = blockIdx.x;
    const int jx = threadIdx.x;
    float m = -3.402823466e38f;
    const float* base = hid + (size_t)b*LX*1024 + jx;
    for (int l = 0; l < LX; l++) m = fmaxf(m, base[(size_t)l*1024]);
    ge[(size_t)b*1024 + jx] = m;
}

// ============================ host launcher ================================
extern "C" void kernel_launch(void* const* d_in, const int* in_sizes, int n_in,
                              void* d_out, int out_size)
{
    const int*   feature_info = (const int*)d_in[0];
    const int*   batch_nodes  = (const int*)d_in[1];
    const int*   fw_adj       = (const int*)d_in[2];
    const int*   bw_adj       = (const int*)d_in[3];
    const float* W_emb        = (const float*)d_in[4];
    const float* Wih_f        = (const float*)d_in[5];
    const float* Whh_f        = (const float*)d_in[6];
    const float* bih_f        = (const float*)d_in[7];
    const float* bhh_f        = (const float*)d_in[8];
    const float* Wih_b        = (const float*)d_in[9];
    const float* Whh_b        = (const float*)d_in[10];
    const float* bih_b        = (const float*)d_in[11];
    const float* bhh_b        = (const float*)d_in[12];
    const float* padding_vec  = (const float*)d_in[13];
    const float* fw_W         = (const float*)d_in[14];
    const float* fw_b         = (const float*)d_in[15];
    const float* bw_W         = (const float*)d_in[16];
    const float* bw_b         = (const float*)d_in[17];
    float* out = (float*)d_out;

    const int DSMEM = 2*65536 + 1024;
    cudaFuncSetAttribute(k_mma_gemm, cudaFuncAttributeMaxDynamicSharedMemorySize, DSMEM);

    float *p_nrep, *p_hid, *p_len, *p_bias, *p_xp;
    __nv_bfloat16 *p_embh, *p_embl, *p_wihh, *p_wihl, *p_wh, *p_wl, *p_cath, *p_catl;
    cudaGetSymbolAddress((void**)&p_nrep, g_nrep);
    cudaGetSymbolAddress((void**)&p_hid,  g_hid);
    cudaGetSymbolAddress((void**)&p_len,  g_len);
    cudaGetSymbolAddress((void**)&p_bias, g_bias);
    cudaGetSymbolAddress((void**)&p_xp,   g_xp);
    cudaGetSymbolAddress((void**)&p_embh, g_embh);
    cudaGetSymbolAddress((void**)&p_embl, g_embl);
    cudaGetSymbolAddress((void**)&p_wihh, g_wihh);
    cudaGetSymbolAddress((void**)&p_wihl, g_wihl);
    cudaGetSymbolAddress((void**)&p_wh,   g_wh);
    cudaGetSymbolAddress((void**)&p_wl,   g_wl);
    cudaGetSymbolAddress((void**)&p_cath, g_cath);
    cudaGetSymbolAddress((void**)&p_catl, g_catl);

    float* hid_d[2][2];
    for (int d = 0; d < 2; d++)
        for (int q = 0; q < 2; q++)
            hid_d[d][q] = p_hid + ((size_t)d*2 + q) * ((size_t)(NX+1)*HX);

    // 1. embed + weight preprocessing
    k_embed<<<(NX*EMBP + 255)/256, 256>>>(feature_info, W_emb);
    k_bias<<<4, 256>>>(bih_f, bhh_f, bih_b, bhh_b);
    k_split_wih<<<(2*1024*EMBP + 255)/256, 256>>>(Wih_f, Wih_b);
    k_split_sagew<<<(2*LAYERSX*HX*K_SAGE + 255)/256, 256>>>(fw_W, bw_W);
    k_whhq<<<(2*HHX*HHX + 255)/256, 256>>>(Whh_f, Whh_b);

    // 2. input projections via mma.sync (bf16x3)
    dim3 gxp(1024/128, NX/128);
    k_mma_gemm<<<gxp, 256, DSMEM>>>(p_embh, p_embl, p_wihh, p_wihl,
                                    p_bias, p_xp, 1024, EMBP, 0);
    k_mma_gemm<<<gxp, 256, DSMEM>>>(p_embh, p_embl, p_wihh + (size_t)1024*EMBP,
                                    p_wihl + (size_t)1024*EMBP,
                                    p_bias + 1024, p_xp + (size_t)NX*1024, 1024, EMBP, 0);

    // 3. persistent BiLSTM -> g_nrep rows 0..N-1
    k_lstm<<<64, 256>>>();

    // 4. padding row / zero rows / init hidden / neighbor lengths
    k_pad_zero<<<1, 512>>>(padding_vec);
    k_init_hid<<<(NX*HX + 255)/256, 256>>>(batch_nodes);
    k_len<<<dim3(NX, 2), 128>>>(batch_nodes, fw_adj, bw_adj);

    // 5. 7 SAGE layers x 2 directions (mma.sync bf16x3)
    int pin = 0;
    dim3 gsage(HX/128, NX/128);
    for (int l = 0; l < LAYERSX; l++) {
        for (int d = 0; d < 2; d++) {
            const float* neighT = (l == 0) ? p_nrep : hid_d[d][pin];
            const int*   adj    = d ? bw_adj : fw_adj;
            k_gm<<<NX, 128>>>(hid_d[d][pin], neighT, batch_nodes, adj,
                              p_len + (size_t)d*NX);
            const __nv_bfloat16* Wh = p_wh + ((size_t)d*LAYERSX + l)*HX*K_SAGE;
            const __nv_bfloat16* Wl = p_wl + ((size_t)d*LAYERSX + l)*HX*K_SAGE;
            const float* bb = (d ? bw_b : fw_b) + (size_t)l*HX;
            k_mma_gemm<<<gsage, 256, DSMEM>>>(p_cath, p_catl, Wh, Wl, bb,
                                              hid_d[d][1 - pin], HX, K_SAGE, 1);
        }
        pin ^= 1;
    }

    // 6. outputs
    k_finalize<<<(NX*HX + 255)/256, 256>>>(out, pin);
    k_pool<<<BX, 1024>>>(out, out + OFF_GE);
    (void)in_sizes; (void)n_in; (void)out_size;
}

// round 7
// speedup vs baseline: 2.3725x; 1.0489x over previous
#include <cuda_runtime.h>
#include <cuda_bf16.h>
#include <math.h>
#include <stdint.h>

#define EMBX 300
#define EMBP 320
#define HX 512
#define HHX 256
#define BX 128
#define LX 128
#define NX (BX*LX)          /* 16384 */
#define SX 10
#define LAYERSX 7
#define K_SAGE 1024

#define SZ_HID (NX*2*HX)
#define OFF_GE SZ_HID
#define OFF_OV (SZ_HID + 2*BX*HX)

// ---------------- scratch (device globals) ----------------
__device__ __align__(16) __nv_bfloat16 g_embh[(size_t)NX*EMBP];
__device__ __align__(16) __nv_bfloat16 g_embl[(size_t)NX*EMBP];
__device__ __align__(16) __nv_bfloat16 g_wihh[2][(size_t)1024*EMBP];
__device__ __align__(16) __nv_bfloat16 g_wihl[2][(size_t)1024*EMBP];
__device__ __align__(16) __nv_bfloat16 g_wh[2][LAYERSX][(size_t)HX*K_SAGE];
__device__ __align__(16) __nv_bfloat16 g_wl[2][LAYERSX][(size_t)HX*K_SAGE];
__device__ __align__(16) __nv_bfloat16 g_cath[2][(size_t)NX*K_SAGE];
__device__ __align__(16) __nv_bfloat16 g_catl[2][(size_t)NX*K_SAGE];
__device__ __align__(16) float g_xp[2][(size_t)NX*1024];
__device__ __align__(16) float g_nrep[(size_t)(NX+1)*HX];
__device__ __align__(16) float g_hid[2][2][(size_t)(NX+1)*HX];
__device__ __align__(16) float g_len[2][NX];
__device__ __align__(16) float g_bias[2][1024];
__device__ __align__(16) float g_sbias[2][LAYERSX*HX];
__device__ __align__(16) float g_whhq[2][HHX*HHX*4];

// ---------------- helpers ----------------
#define SWZ(o) ((o) ^ (((o) >> 3) & 0x70))

__device__ __forceinline__ uint32_t s2u(const void* p) {
    uint32_t a;
    asm("{ .reg .u64 t; cvta.to.shared.u64 t, %1; cvt.u32.u64 %0, t; }"
        : "=r"(a) : "l"(p));
    return a;
}
__device__ __forceinline__ void cpa16(uint32_t d, const void* g) {
    asm volatile("cp.async.cg.shared.global [%0], [%1], 16;" :: "r"(d), "l"(g));
}
__device__ __forceinline__ void ldsm4(uint32_t* r, uint32_t addr) {
    asm volatile("ldmatrix.sync.aligned.m8n8.x4.shared.b16 {%0,%1,%2,%3}, [%4];"
        : "=r"(r[0]), "=r"(r[1]), "=r"(r[2]), "=r"(r[3]) : "r"(addr));
}
__device__ __forceinline__ void mma16816(float* d, const uint32_t* a, const uint32_t* b) {
    asm volatile("mma.sync.aligned.m16n8k16.row.col.f32.bf16.bf16.f32 "
        "{%0,%1,%2,%3}, {%4,%5,%6,%7}, {%8,%9}, {%0,%1,%2,%3};"
        : "+f"(d[0]), "+f"(d[1]), "+f"(d[2]), "+f"(d[3])
        : "r"(a[0]), "r"(a[1]), "r"(a[2]), "r"(a[3]), "r"(b[0]), "r"(b[1]));
}
__device__ __forceinline__ void bsplit(float a, __nv_bfloat16& h, __nv_bfloat16& l) {
    h = __float2bfloat16(a);
    l = __float2bfloat16(a - __bfloat162float(h));
}

// ---------------- embedding lookup -> bf16 hi/lo, K padded to 320 ----------
__global__ void k_embed(const int* __restrict__ feat, const float* __restrict__ Wemb)
{
    int idx = blockIdx.x * blockDim.x + threadIdx.x;
    if (idx >= NX*EMBP) return;
    int n = idx / EMBP, e = idx - n*EMBP;
    float v = 0.f;
    if (e < EMBX) v = Wemb[(size_t)feat[n]*EMBX + e];
    __nv_bfloat16 h, l; bsplit(v, h, l);
    g_embh[idx] = h; g_embl[idx] = l;
}

// ---------------- bias precompute: bih+bhh, packed SAGE biases -------------
__global__ void k_bias(const float* bihf, const float* bhhf,
                       const float* bihb, const float* bhhb,
                       const float* fwb, const float* bwb)
{
    int j = blockIdx.x * blockDim.x + threadIdx.x;
    if (j < 4*HHX) {
        g_bias[0][j] = bihf[j] + bhhf[j];
        g_bias[1][j] = bihb[j] + bhhb[j];
    }
    if (j < LAYERSX*HX) {
        g_sbias[0][j] = fwb[j];
        g_sbias[1][j] = bwb[j];
    }
}

// ---------------- Wih split -> bf16 hi/lo, padded to 320 -------------------
__global__ void k_split_wih(const float* __restrict__ Wf, const float* __restrict__ Wb)
{
    int idx = blockIdx.x * blockDim.x + threadIdx.x;
    if (idx >= 2*1024*EMBP) return;
    int d = idx / (1024*EMBP);
    int rem = idx - d*(1024*EMBP);
    int r = rem / EMBP, e = rem - r*EMBP;
    const float* W = d ? Wb : Wf;
    float v = (e < EMBX) ? W[(size_t)r*EMBX + e] : 0.f;
    __nv_bfloat16 h, l; bsplit(v, h, l);
    g_wihh[d][rem] = h; g_wihl[d][rem] = l;
}

// ---------------- SAGE W split -> bf16 hi/lo -------------------------------
__global__ void k_split_sagew(const float* __restrict__ Wf, const float* __restrict__ Wb)
{
    const int per = LAYERSX*HX*K_SAGE;
    int idx = blockIdx.x * blockDim.x + threadIdx.x;
    if (idx >= 2*per) return;
    int d = idx / per, rem = idx - d*per;
    float v = (d ? Wb : Wf)[rem];
    __nv_bfloat16 h, l; bsplit(v, h, l);
    (&g_wh[0][0][0])[(size_t)d*per + rem] = h;
    (&g_wl[0][0][0])[(size_t)d*per + rem] = l;
}

// ---------------- Whh transpose into [k][j][{i,f,g,o}] float4 layout --------
__global__ void k_whhq(const float* __restrict__ Wf, const float* __restrict__ Wb)
{
    int idx = blockIdx.x * blockDim.x + threadIdx.x;
    if (idx >= 2*HHX*HHX) return;
    int d = idx / (HHX*HHX);
    int rem = idx - d*(HHX*HHX);
    int k = rem / HHX, j = rem - k*HHX;
    const float* W = d ? Wb : Wf;
    float4 v;
    v.x = W[(size_t)(0*HHX + j)*HHX + k];
    v.y = W[(size_t)(1*HHX + j)*HHX + k];
    v.z = W[(size_t)(2*HHX + j)*HHX + k];
    v.w = W[(size_t)(3*HHX + j)*HHX + k];
    *(float4*)&g_whhq[d][(size_t)rem*4] = v;
}

// ============ mma.sync bf16x3 GEMM, dual-direction via blockIdx.z ==========
// A: M x K bf16 hi/lo (K-major), B: Ncols x K bf16 hi/lo (K-major), C fp32.
// Tile 128x128, BK=64 (128B rows, SW128 swizzle), 3-stage cp.async pipeline.
// Stage layout: Ah @0, Al @16K, Bh @32K, Bl @48K (each 128 rows x 128B).
__device__ __forceinline__ void load_stage(
    uint32_t sb, int s, int kc,
    const char* A0, const char* A1, const char* B0, const char* B1,
    int K, int tid)
{
    const char* srcs[4] = { A0, A1, B0, B1 };
    uint32_t stb = sb + s*65536;
#pragma unroll
    for (int t4 = 0; t4 < 4; t4++) {
        const char* src = srcs[t4] + (size_t)kc*128;
        uint32_t tb = stb + t4*16384;
#pragma unroll
        for (int i = 0; i < 4; i++) {
            int q = tid + i*256;
            int r = q >> 3, sc = q & 7;
            cpa16(tb + SWZ(r*128 + sc*16), src + (size_t)r*(size_t)K*2 + sc*16);
        }
    }
    asm volatile("cp.async.commit_group;" ::: "memory");
}

__global__ __launch_bounds__(256, 1) void k_mma_gemm(
    const __nv_bfloat16* __restrict__ Ah, const __nv_bfloat16* __restrict__ Al,
    const __nv_bfloat16* __restrict__ Bh, const __nv_bfloat16* __restrict__ Bl,
    const float* __restrict__ bias, float* __restrict__ C,
    int Ncols, int K, int relu,
    size_t sA, size_t sB, size_t sBias, size_t sC)
{
    extern __shared__ char dsm[];
    const int z = blockIdx.z;
    Ah += (size_t)z*sA;  Al += (size_t)z*sA;
    Bh += (size_t)z*sB;  Bl += (size_t)z*sB;
    bias += (size_t)z*sBias;
    C  += (size_t)z*sC;

    const int tid = threadIdx.x;
    const int wid = tid >> 5, lane = tid & 31;
    const int row0 = blockIdx.y << 7;
    const int col0 = blockIdx.x << 7;
    const int nch = K >> 6;

    uint32_t sb = s2u(dsm);
    sb = (sb + 1023u) & ~1023u;

    const char* A0 = (const char*)(Ah + (size_t)row0*K);
    const char* A1 = (const char*)(Al + (size_t)row0*K);
    const char* B0 = (const char*)(Bh + (size_t)col0*K);
    const char* B1 = (const char*)(Bl + (size_t)col0*K);

    // warp tile: 32 rows x 64 cols; 8 warps = 4x2
    const int wm = (wid >> 1) * 32;
    const int wn = (wid & 1) * 64;

    // ldmatrix lane -> (row, 16B-col) within tile
    const int gq8 = lane >> 3, lr = lane & 7;
    const int a_row = wm + lr + ((gq8 & 1) << 3);
    const int a_cb  = (gq8 >> 1) << 4;
    const int b_row = wn + lr + ((gq8 >> 1) << 3);
    const int b_cb  = (gq8 & 1) << 4;

    float acc[2][8][4];
#pragma unroll
    for (int mt = 0; mt < 2; mt++)
#pragma unroll
        for (int nt = 0; nt < 8; nt++)
#pragma unroll
            for (int j = 0; j < 4; j++) acc[mt][nt][j] = 0.f;

    load_stage(sb, 0, 0, A0, A1, B0, B1, K, tid);
    if (nch > 1) load_stage(sb, 1, 1, A0, A1, B0, B1, K, tid);

    int sidx = 0;
    for (int kc = 0; kc < nch; kc++) {
        if (kc + 1 < nch)
            asm volatile("cp.async.wait_group 1;" ::: "memory");
        else
            asm volatile("cp.async.wait_group 0;" ::: "memory");
        __syncthreads();
        if (kc + 2 < nch) {
            int ls = sidx + 2; if (ls >= 3) ls -= 3;
            load_stage(sb, ls, kc + 2, A0, A1, B0, B1, K, tid);
        }
        const uint32_t stb = sb + sidx*65536;
#pragma unroll
        for (int ks = 0; ks < 4; ks++) {
            const int k0b = ks * 32;
            uint32_t ah[2][4], al[2][4];
#pragma unroll
            for (int mt = 0; mt < 2; mt++) {
                uint32_t off = SWZ((uint32_t)((a_row + mt*16)*128 + (a_cb + k0b)));
                ldsm4(ah[mt], stb + off);
                ldsm4(al[mt], stb + 16384 + off);
            }
            uint32_t bh[4][4], bl[4][4];
#pragma unroll
            for (int gg = 0; gg < 4; gg++) {
                uint32_t off = SWZ((uint32_t)((b_row + gg*16)*128 + (b_cb + k0b)));
                ldsm4(bh[gg], stb + 32768 + off);
                ldsm4(bl[gg], stb + 49152 + off);
            }
#pragma unroll
            for (int mt = 0; mt < 2; mt++)
#pragma unroll
                for (int nt = 0; nt < 8; nt++) {
                    const uint32_t* bhp = &bh[nt >> 1][(nt & 1) * 2];
                    const uint32_t* blp = &bl[nt >> 1][(nt & 1) * 2];
                    mma16816(acc[mt][nt], ah[mt], bhp);
                    mma16816(acc[mt][nt], ah[mt], blp);
                    mma16816(acc[mt][nt], al[mt], bhp);
                }
        }
        sidx++; if (sidx >= 3) sidx = 0;
    }

    // epilogue: acc -> C with bias (+relu)
    const int erow = row0 + wm + (lane >> 2);
    const int ecol = col0 + wn + 2*(lane & 3);
#pragma unroll
    for (int mt = 0; mt < 2; mt++)
#pragma unroll
        for (int nt = 0; nt < 8; nt++) {
            int r = erow + mt*16;
            int cc = ecol + nt*8;
            float2 v0, v1;
            v0.x = acc[mt][nt][0] + bias[cc];
            v0.y = acc[mt][nt][1] + bias[cc+1];
            v1.x = acc[mt][nt][2] + bias[cc];
            v1.y = acc[mt][nt][3] + bias[cc+1];
            if (relu) {
                v0.x = fmaxf(v0.x, 0.f); v0.y = fmaxf(v0.y, 0.f);
                v1.x = fmaxf(v1.x, 0.f); v1.y = fmaxf(v1.y, 0.f);
            }
            *(float2*)&C[(size_t)r*Ncols + cc]     = v0;
            *(float2*)&C[(size_t)(r+8)*Ncols + cc] = v1;
        }
}

// ---------------- persistent BiLSTM ----------------
__global__ __launch_bounds__(256) void k_lstm()
{
    const int dir = blockIdx.x >> 5;
    const int rg  = blockIdx.x & 31;
    const int j = threadIdx.x;
    const float* __restrict__ Wq = g_whhq[dir];
    const float* __restrict__ xp = g_xp[dir];
    __shared__ float hbuf[2][4][HHX];
#pragma unroll
    for (int r = 0; r < 4; r++) hbuf[0][r][j] = 0.f;
    float c[4] = {0.f, 0.f, 0.f, 0.f};
    __syncthreads();
    int p = 0;
    for (int t = 0; t < LX; t++) {
        const int tseq = dir ? (LX - 1 - t) : t;
        float a0[4] = {0,0,0,0}, a1[4] = {0,0,0,0};
        float a2[4] = {0,0,0,0}, a3[4] = {0,0,0,0};
#pragma unroll 4
        for (int k = 0; k < HHX; k++) {
            float4 w = *(const float4*)&Wq[((size_t)k*HHX + j)*4];
#pragma unroll
            for (int r = 0; r < 4; r++) {
                float hv = hbuf[p][r][k];
                a0[r] = fmaf(w.x, hv, a0[r]);
                a1[r] = fmaf(w.y, hv, a1[r]);
                a2[r] = fmaf(w.z, hv, a2[r]);
                a3[r] = fmaf(w.w, hv, a3[r]);
            }
        }
#pragma unroll
        for (int r = 0; r < 4; r++) {
            const int row = rg*4 + r;
            const size_t nidx = (size_t)row*LX + tseq;
            const float* xr = xp + nidx*(4*HHX);
            float gi = a0[r] + xr[j];
            float gf = a1[r] + xr[HHX + j];
            float gg = a2[r] + xr[2*HHX + j];
            float go = a3[r] + xr[3*HHX + j];
            float si = 1.f/(1.f + expf(-gi));
            float sf = 1.f/(1.f + expf(-gf));
            float so = 1.f/(1.f + expf(-go));
            float tg = tanhf(gg);
            c[r] = sf*c[r] + si*tg;
            float hv = so * tanhf(c[r]);
            hbuf[p ^ 1][r][j] = hv;
            g_nrep[nidx*HX + (size_t)dir*HHX + j] = hv;
        }
        __syncthreads();
        p ^= 1;
    }
}

// ---------------- padding row + zero row N of hidden buffers ----------------
__global__ void k_pad_zero(const float* __restrict__ pad)
{
    int j = threadIdx.x;
    if (j < HX) {
        g_nrep[(size_t)NX*HX + j] = pad[j];
        g_hid[0][0][(size_t)NX*HX + j] = 0.f;
        g_hid[0][1][(size_t)NX*HX + j] = 0.f;
        g_hid[1][0][(size_t)NX*HX + j] = 0.f;
        g_hid[1][1][(size_t)NX*HX + j] = 0.f;
    }
}

// ---------------- initial hidden = node_repres[batch_nodes] ----------------
__global__ void k_init_hid(const int* __restrict__ nodes)
{
    int idx = blockIdx.x * blockDim.x + threadIdx.x;
    if (idx >= NX*HX) return;
    int n = idx >> 9, cc = idx & (HX - 1);
    float v = g_nrep[(size_t)nodes[n]*HX + cc];
    g_hid[0][0][idx] = v;
    g_hid[1][0][idx] = v;
}

// ------- gather + mean + concat -> bf16 hi/lo cat; optional len compute ----
// grid (NX, 2): blockIdx.y = direction. Layer 0 also computes neighbor count.
__global__ __launch_bounds__(128) void k_gm(
    const float* __restrict__ selfT, size_t sSelf,
    const float* __restrict__ neighT, size_t sNeigh,
    const int* __restrict__ nodes,
    const int* __restrict__ adjF, const int* __restrict__ adjB,
    int computeLen)
{
    const int n = blockIdx.x;
    const int dir = blockIdx.y;
    selfT  += (size_t)dir*sSelf;
    neighT += (size_t)dir*sNeigh;
    const int* adj = dir ? adjB : adjF;
    __nv_bfloat16* cath = g_cath[dir];
    __nv_bfloat16* catl = g_catl[dir];

    const int t = threadIdx.x;
    __shared__ int nb[SX];
    __shared__ float s_red[4][SX];
    __shared__ float s_inv;
    if (t < SX) nb[t] = adj[(size_t)nodes[n]*SX + t];
    if (!computeLen && t == 0) s_inv = 1.f / g_len[dir][n];
    __syncthreads();

    const int c = t * 4;
    float4 s = {0.f, 0.f, 0.f, 0.f};
    float rq[SX];
#pragma unroll
    for (int q = 0; q < SX; q++) {
        const float4 v = *(const float4*)&neighT[(size_t)nb[q]*HX + c];
        s.x += v.x; s.y += v.y; s.z += v.z; s.w += v.w;
        if (computeLen) {
            rq[q] = fmaxf(v.x, 0.f) + fmaxf(v.y, 0.f)
                  + fmaxf(v.z, 0.f) + fmaxf(v.w, 0.f);
        }
    }
    if (computeLen) {
        const int lane = t & 31, w = t >> 5;
#pragma unroll
        for (int q = 0; q < SX; q++) {
            float x = rq[q];
#pragma unroll
            for (int o = 16; o; o >>= 1) x += __shfl_xor_sync(0xffffffffu, x, o);
            if (lane == 0) s_red[w][q] = x;
        }
        __syncthreads();
        if (t == 0) {
            float cnt = 0.f;
#pragma unroll
            for (int q = 0; q < SX; q++) {
                float tot = s_red[0][q] + s_red[1][q] + s_red[2][q] + s_red[3][q];
                if (tot > 0.f) cnt += 1.f;
            }
            g_len[dir][n] = cnt;
            s_inv = 1.f / cnt;
        }
        __syncthreads();
    }
    const float invlen = s_inv;

    float4 sv = *(const float4*)&selfT[(size_t)n*HX + c];
    float4 m = {s.x*invlen, s.y*invlen, s.z*invlen, s.w*invlen};

    size_t o = (size_t)n*K_SAGE + c;
    __nv_bfloat16 h0,l0,h1,l1,h2,l2,h3,l3;
    bsplit(sv.x,h0,l0); bsplit(sv.y,h1,l1); bsplit(sv.z,h2,l2); bsplit(sv.w,h3,l3);
    *(__nv_bfloat162*)&cath[o]   = __halves2bfloat162(h0,h1);
    *(__nv_bfloat162*)&cath[o+2] = __halves2bfloat162(h2,h3);
    *(__nv_bfloat162*)&catl[o]   = __halves2bfloat162(l0,l1);
    *(__nv_bfloat162*)&catl[o+2] = __halves2bfloat162(l2,l3);

    bsplit(m.x,h0,l0); bsplit(m.y,h1,l1); bsplit(m.z,h2,l2); bsplit(m.w,h3,l3);
    *(__nv_bfloat162*)&cath[o+HX]   = __halves2bfloat162(h0,h1);
    *(__nv_bfloat162*)&cath[o+HX+2] = __halves2bfloat162(h2,h3);
    *(__nv_bfloat162*)&catl[o+HX]   = __halves2bfloat162(l0,l1);
    *(__nv_bfloat162*)&catl[o+HX+2] = __halves2bfloat162(l2,l3);
}

// ---------------- finalize + pool ----------------
__global__ void k_finalize(float* __restrict__ out, int fin)
{
    int idx = blockIdx.x * blockDim.x + threadIdx.x;
    if (idx >= NX*HX) return;
    int n = idx >> 9, cc = idx & (HX - 1);
    out[(size_t)n*1024 + cc]       = g_hid[0][fin][idx];
    out[(size_t)n*1024 + 512 + cc] = g_hid[1][fin][idx];
    out[(size_t)OFF_OV + idx]      = g_nrep[idx];
}

__global__ void k_pool(const float* __restrict__ hid, float* __restrict__ ge)
{
    const int b = blockIdx.x;
    const int jx = threadIdx.x;
    float m = -3.402823466e38f;
    const float* base = hid + (size_t)b*LX*1024 + jx;
    for (int l = 0; l < LX; l++) m = fmaxf(m, base[(size_t)l*1024]);
    ge[(size_t)b*1024 + jx] = m;
}

// ============================ host launcher ================================
extern "C" void kernel_launch(void* const* d_in, const int* in_sizes, int n_in,
                              void* d_out, int out_size)
{
    const int*   feature_info = (const int*)d_in[0];
    const int*   batch_nodes  = (const int*)d_in[1];
    const int*   fw_adj       = (const int*)d_in[2];
    const int*   bw_adj       = (const int*)d_in[3];
    const float* W_emb        = (const float*)d_in[4];
    const float* Wih_f        = (const float*)d_in[5];
    const float* Whh_f        = (const float*)d_in[6];
    const float* bih_f        = (const float*)d_in[7];
    const float* bhh_f        = (const float*)d_in[8];
    const float* Wih_b        = (const float*)d_in[9];
    const float* Whh_b        = (const float*)d_in[10];
    const float* bih_b        = (const float*)d_in[11];
    const float* bhh_b        = (const float*)d_in[12];
    const float* padding_vec  = (const float*)d_in[13];
    const float* fw_W         = (const float*)d_in[14];
    const float* fw_b         = (const float*)d_in[15];
    const float* bw_W         = (const float*)d_in[16];
    const float* bw_b         = (const float*)d_in[17];
    float* out = (float*)d_out;

    const int DSMEM = 3*65536 + 1024;
    cudaFuncSetAttribute(k_mma_gemm, cudaFuncAttributeMaxDynamicSharedMemorySize, DSMEM);

    float *p_nrep, *p_hid, *p_bias, *p_sbias, *p_xp;
    __nv_bfloat16 *p_embh, *p_embl, *p_wihh, *p_wihl, *p_wh, *p_wl, *p_cath, *p_catl;
    cudaGetSymbolAddress((void**)&p_nrep, g_nrep);
    cudaGetSymbolAddress((void**)&p_hid,  g_hid);
    cudaGetSymbolAddress((void**)&p_bias, g_bias);
    cudaGetSymbolAddress((void**)&p_sbias,g_sbias);
    cudaGetSymbolAddress((void**)&p_xp,   g_xp);
    cudaGetSymbolAddress((void**)&p_embh, g_embh);
    cudaGetSymbolAddress((void**)&p_embl, g_embl);
    cudaGetSymbolAddress((void**)&p_wihh, g_wihh);
    cudaGetSymbolAddress((void**)&p_wihl, g_wihl);
    cudaGetSymbolAddress((void**)&p_wh,   g_wh);
    cudaGetSymbolAddress((void**)&p_wl,   g_wl);
    cudaGetSymbolAddress((void**)&p_cath, g_cath);
    cudaGetSymbolAddress((void**)&p_catl, g_catl);

    const size_t HIDQ = (size_t)(NX+1)*HX;        // per-buffer stride
    const size_t HIDD = 2*HIDQ;                   // dir stride
    float* hid_d[2][2];
    for (int d = 0; d < 2; d++)
        for (int q = 0; q < 2; q++)
            hid_d[d][q] = p_hid + ((size_t)d*2 + q)*HIDQ;

    // 1. embed + weight preprocessing
    k_embed<<<(NX*EMBP + 255)/256, 256>>>(feature_info, W_emb);
    k_bias<<<(LAYERSX*HX + 255)/256, 256>>>(bih_f, bhh_f, bih_b, bhh_b, fw_b, bw_b);
    k_split_wih<<<(2*1024*EMBP + 255)/256, 256>>>(Wih_f, Wih_b);
    k_split_sagew<<<(2*LAYERSX*HX*K_SAGE + 255)/256, 256>>>(fw_W, bw_W);
    k_whhq<<<(2*HHX*HHX + 255)/256, 256>>>(Whh_f, Whh_b);

    // 2. input projections, both dirs in one launch (bf16x3 mma)
    dim3 gxp(1024/128, NX/128, 2);
    k_mma_gemm<<<gxp, 256, DSMEM>>>(p_embh, p_embl, p_wihh, p_wihl,
                                    p_bias, p_xp, 1024, EMBP, 0,
                                    0, (size_t)1024*EMBP, 1024, (size_t)NX*1024);

    // 3. persistent BiLSTM -> g_nrep rows 0..N-1
    k_lstm<<<64, 256>>>();

    // 4. padding row / zero rows / init hidden
    k_pad_zero<<<1, 512>>>(padding_vec);
    k_init_hid<<<(NX*HX + 255)/256, 256>>>(batch_nodes);

    // 5. 7 SAGE layers, both dirs per launch; layer 0 fuses len computation
    int pin = 0;
    dim3 ggm(NX, 2);
    dim3 gsage(HX/128, NX/128, 2);
    for (int l = 0; l < LAYERSX; l++) {
        if (l == 0)
            k_gm<<<ggm, 128>>>(hid_d[0][pin], HIDD, p_nrep, 0,
                               batch_nodes, fw_adj, bw_adj, 1);
        else
            k_gm<<<ggm, 128>>>(hid_d[0][pin], HIDD, hid_d[0][pin], HIDD,
                               batch_nodes, fw_adj, bw_adj, 0);
        k_mma_gemm<<<gsage, 256, DSMEM>>>(
            p_cath, p_catl,
            p_wh + (size_t)l*HX*K_SAGE, p_wl + (size_t)l*HX*K_SAGE,
            p_sbias + (size_t)l*HX, hid_d[0][1 - pin],
            HX, K_SAGE, 1,
            (size_t)NX*K_SAGE, (size_t)LAYERSX*HX*K_SAGE,
            (size_t)LAYERSX*HX, HIDD);
        pin ^= 1;
    }

    // 6. outputs
    k_finalize<<<(NX*HX + 255)/256, 256>>>(out, pin);
    k_pool<<<BX, 1024>>>(out, out + OFF_GE);
    (void)in_sizes; (void)n_in; (void)out_size;
}